// round 15
// baseline (speedup 1.0000x reference)
#include <cuda_runtime.h>
#include <cstdint>

// CutOutput: per-row (8192 rows) stable descending argsort of D=1571 fp32,
// out[row][r] = (float)index_at_rank_r if r < len else 0, len = base[row].
// Output float32. Stability via packed-u64 (kk<<11)|idx tie-break.
//
// R15 = R14 (best, 84.0us) + three register-neutral cuts:
//  * atomic-prune margin 160 -> 96 (~5 sigma; exact fallback retained).
//  * scan restricted to the live warp-prefix (128*warp <= T): startb above T
//    is never read (scatter dead-tests bk>=T in registers; verify reads
//    startb[T]). Warp-uniform predicate -> shfl stays full-warp-legal.
//  * 3-op monotone key transform: kk = u ^ 0x7FFFFFFF ^ ((u>>31 arith)>>1).
// __launch_bounds__(512,4) pins the 32-reg / 4-block RF point (R12 lesson).

static constexpr int D = 1571;
static constexpr int NB = 2048;
static constexpr int THREADS = 512;
static constexpr int NE = 512;  // octave-table entries (e = kk>>23, 9 bits)

__device__ unsigned g_pack[NE];  // per-octave: b0 | (span << 16)

__global__ void build_base_kernel() {
  const int t = threadIdx.x;
  if (t < NE) {
    auto edge = [](unsigned tt) -> unsigned {
      if (tt >= NE) return NB;
      const unsigned kk0 = tt << 23;
      const unsigned a = ~kk0;
      const unsigned u = (a & 0x80000000u) ? (a ^ 0x80000000u) : ~a;
      const float x = __uint_as_float(u);
      const float c = 0.5f * erfcf(x * 0.70710678118f);  // P(N(0,1) > x)
      unsigned b = (unsigned)(c * (float)NB);
      return b > (NB - 1u) ? (NB - 1u) : b;
    };
    const unsigned b0 = edge(t);
    const unsigned b1 = edge(t + 1);
    g_pack[t] = b0 | ((b1 - b0) << 16);
  }
}

__global__ void __launch_bounds__(THREADS, 4) cutoutput_bucket_kernel(
    const float* __restrict__ to_cut,
    const int* __restrict__ candA,
    const int* __restrict__ candB,
    float* __restrict__ out) {
  __shared__ unsigned long long data[D];        // bucketed (kk<<11)|idx
  __shared__ unsigned pbase[NE];                // packed octave table
  __shared__ alignas(16) unsigned startb[NB + 4];  // packed start | cnt<<16
  __shared__ alignas(16) unsigned hist[NB];
  __shared__ unsigned wsum[16];
  __shared__ alignas(16) float staged[D + 1];   // rank -> (float)idx

  const int t = threadIdx.x;
  const int row = blockIdx.x;
  const float* __restrict__ src = to_cut + (size_t)row * D;

  // base vs ids disambiguation: ids[0] == 0 always; base[0] >= 1 always.
  const int* __restrict__ basep = (candA[0] == 0) ? candB : candA;
  const unsigned len = (unsigned)basep[row];

  // Atomic-pruning threshold (~5 sigma margin; verified exactly below).
  unsigned T = (unsigned)(((unsigned long long)(len + 96u) * NB) / D + 1u);
  if (T > NB) T = NB;

  // ---- copy table (NE == THREADS: unconditional); clear histogram ----
  pbase[t] = g_pack[t];
  reinterpret_cast<uint4*>(hist)[t] = make_uint4(0u, 0u, 0u, 0u);
  __syncthreads();

  // ---- phase 1: load, key, bucket; histogram atomic ONLY for bk < T ----
  unsigned kks[4];
  unsigned short bks[4];
  unsigned short ords[4];
#pragma unroll
  for (int k = 0; k < 4; ++k) {
    const int v = t + k * THREADS;
    if (v < D) {
      const unsigned u = __float_as_uint(src[v]);
      // 3-op monotone transform: ascending kk == descending float value
      const unsigned kk =
          u ^ 0x7FFFFFFFu ^ (((unsigned)((int)u >> 31)) >> 1);
      const unsigned pk = pbase[kk >> 23];
      const unsigned b0 = pk & 0xFFFFu;
      const unsigned n = pk >> 16;
      const unsigned m = (kk >> 7) & 0xFFFFu;
      const unsigned bk = b0 + ((m * n) >> 16);   // exact monotone in kk
      kks[k] = kk;
      bks[k] = (unsigned short)bk;
      ords[k] = (bk < T) ? (unsigned short)atomicAdd(&hist[bk], 1u)
                         : (unsigned short)0;
    }
  }
  __syncthreads();

  // ---- scan over the live warp-prefix only (startb above T never read) ----
  for (int attempt = 0; attempt < 2; ++attempt) {
    {
      // Warp w covers startb indices [128w, 128w+127]; needed iff 128w <= T.
      const bool warp_live = ((unsigned)((t >> 5) << 7) <= T);
      unsigned sum = 0, v = 0;
      uint4 h4;
      if (warp_live) {
        h4 = reinterpret_cast<const uint4*>(hist)[t];
        sum = h4.x + h4.y + h4.z + h4.w;
        v = sum;
#pragma unroll
        for (int d = 1; d < 32; d <<= 1) {
          unsigned nbr = __shfl_up_sync(0xFFFFFFFFu, v, d);
          if ((t & 31) >= d) v += nbr;
        }
        if ((t & 31) == 31) wsum[t >> 5] = v;
      }
      __syncthreads();
      if (t < 16) {
        unsigned w = wsum[t];
#pragma unroll
        for (int d = 1; d < 16; d <<= 1) {
          unsigned nbr = __shfl_up_sync(0xFFFFu, w, d);
          if (t >= d) w += nbr;
        }
        wsum[t] = w;  // garbage beyond live prefix: only read by dead warps
      }
      __syncthreads();
      if (warp_live) {
        const unsigned excl = v - sum + ((t >= 32) ? wsum[(t >> 5) - 1] : 0u);
        reinterpret_cast<uint4*>(startb)[t] = make_uint4(
            excl | (h4.x << 16), (excl + h4.x) | (h4.y << 16),
            (excl + h4.x + h4.y) | (h4.z << 16),
            (excl + h4.x + h4.y + h4.z) | (h4.w << 16));
      }
    }
    __syncthreads();

    if (T >= NB || (startb[T] & 0xFFFFu) >= len) break;  // pruning exact

    // Fallback (prob ~0): count the skipped elements, rescan with T = NB.
    // hist[bk >= T] are still 0 (full clear, untouched by phase 1).
#pragma unroll
    for (int k = 0; k < 4; ++k) {
      const int v = t + k * THREADS;
      if (v < D && bks[k] >= T) {
        ords[k] = (unsigned short)atomicAdd(&hist[bks[k]], 1u);
      }
    }
    T = NB;
    __syncthreads();
  }

  // ---- scatter: dead test in registers; packed LDS only if bk < T ----
#pragma unroll
  for (int k = 0; k < 4; ++k) {
    const int v = t + k * THREADS;
    if (v < D) {
      const unsigned bk = bks[k];
      if (bk >= T) {
        bks[k] = 0xFFFFu;                  // pruned: provably rank >= len
      } else {
        const unsigned pc = startb[bk];    // start | cnt<<16
        const unsigned s = pc & 0xFFFFu;
        if (s >= len) {
          bks[k] = 0xFFFFu;                // dead bucket: output is 0 anyway
        } else if ((pc >> 16) == 1u) {
          staged[s] = (float)v;            // rank known: bucket of one
          bks[k] = 0xFFFFu;
        } else {
          data[s + ords[k]] = ((unsigned long long)kks[k] << 11) | (unsigned)v;
        }
      }
    }
  }
  __syncthreads();

  // ---- phase 2: per-element rank within live multi-element buckets ----
#pragma unroll
  for (int k = 0; k < 4; ++k) {
    const int v = t + k * THREADS;
    if (v < D && bks[k] != 0xFFFFu) {
      const unsigned pc = startb[bks[k]];
      const unsigned s = pc & 0xFFFFu;
      const unsigned e = s + (pc >> 16);
      const unsigned long long ki =
          ((unsigned long long)kks[k] << 11) | (unsigned)v;
      unsigned r = s;
      for (unsigned j = s; j < e; ++j) r += (data[j] < ki) ? 1u : 0u;
      if (r < len) staged[r] = (float)v;
    }
  }
  __syncthreads();

  // ---- output: float4 staged read, masked scalar stores (row base only
  //      4B-aligned in gmem, so no STG.128) ----
  float* __restrict__ dst = out + (size_t)row * D;
  {
    const unsigned r0 = 4u * (unsigned)t;
    if (r0 < D) {
      const float4 sv = reinterpret_cast<const float4*>(staged)[t];
      const float o0 = (r0 < len) ? sv.x : 0.0f;
      const float o1 = (r0 + 1 < len) ? sv.y : 0.0f;
      const float o2 = (r0 + 2 < len) ? sv.z : 0.0f;
      const float o3 = (r0 + 3 < len) ? sv.w : 0.0f;
      dst[r0] = o0;
      if (r0 + 1 < D) dst[r0 + 1] = o1;
      if (r0 + 2 < D) dst[r0 + 2] = o2;
      if (r0 + 3 < D) dst[r0 + 3] = o3;
    }
  }
}

extern "C" void kernel_launch(void* const* d_in, const int* in_sizes, int n_in,
                              void* d_out, int out_size) {
  // to_cut is the (unique) large buffer: P*T*D elements.
  int imax = 0;
  for (int i = 1; i < n_in; ++i)
    if (in_sizes[i] > in_sizes[imax]) imax = i;
  const float* to_cut = (const float*)d_in[imax];

  int others[2], k = 0;
  for (int i = 0; i < n_in && k < 2; ++i)
    if (i != imax) others[k++] = i;
  const int* candA = (const int*)d_in[others[0]];
  const int* candB = (const int*)d_in[others[1]];

  float* out = (float*)d_out;
  const int rows = in_sizes[imax] / D;  // P*T = 8192

  build_base_kernel<<<1, NE>>>();
  cutoutput_bucket_kernel<<<rows, THREADS>>>(to_cut, candA, candB, out);
}

// round 16
// speedup vs baseline: 1.1010x; 1.1010x over previous
#include <cuda_runtime.h>
#include <cstdint>

// CutOutput: per-row (8192 rows) stable descending argsort of D=1571 fp32,
// out[row][r] = (float)index_at_rank_r if r < len else 0, len = base[row].
// Output float32. Stability via packed-u64 (kk<<11)|idx tie-break.
//
// R16 = R14 (best, 84.0us) + ONE structural delta: kill the staged[]
// indirection. Ranks < len are final output positions -> write gmem
// directly (singleton fast path + phase-2). Zero region [len, D) is a
// contiguous coalesced fill issued at kernel START (overlaps phase 1;
// disjoint addresses, no hazard). Deletes ~785 STS + 393 LDS.128 + one
// barrier per block from the L1/LSU stream shared with the atomics.
// Completeness: rank r<len => its bucket start s<=r<len<=startb[T] => bucket
// live AND bk<T, so no prune can drop a live rank (poison coverage exact).
// Plus: atomic-prune margin 160->96 (~5 sigma; exact fallback retained).
// __launch_bounds__(512,4) pins the 32-reg / 4-block RF point.

static constexpr int D = 1571;
static constexpr int NB = 2048;
static constexpr int THREADS = 512;
static constexpr int NE = 512;  // octave-table entries (e = kk>>23, 9 bits)

__device__ unsigned g_pack[NE];  // per-octave: b0 | (span << 16)

__global__ void build_base_kernel() {
  const int t = threadIdx.x;
  if (t < NE) {
    auto edge = [](unsigned tt) -> unsigned {
      if (tt >= NE) return NB;
      const unsigned kk0 = tt << 23;
      const unsigned a = ~kk0;
      const unsigned u = (a & 0x80000000u) ? (a ^ 0x80000000u) : ~a;
      const float x = __uint_as_float(u);
      const float c = 0.5f * erfcf(x * 0.70710678118f);  // P(N(0,1) > x)
      unsigned b = (unsigned)(c * (float)NB);
      return b > (NB - 1u) ? (NB - 1u) : b;
    };
    const unsigned b0 = edge(t);
    const unsigned b1 = edge(t + 1);
    g_pack[t] = b0 | ((b1 - b0) << 16);
  }
}

__global__ void __launch_bounds__(THREADS, 4) cutoutput_bucket_kernel(
    const float* __restrict__ to_cut,
    const int* __restrict__ candA,
    const int* __restrict__ candB,
    float* __restrict__ out) {
  __shared__ unsigned long long data[D];        // bucketed (kk<<11)|idx
  __shared__ unsigned pbase[NE];                // packed octave table
  __shared__ alignas(16) unsigned startb[NB + 4];  // packed start | cnt<<16
  __shared__ alignas(16) unsigned hist[NB];
  __shared__ unsigned wsum[16];

  const int t = threadIdx.x;
  const int row = blockIdx.x;
  const float* __restrict__ src = to_cut + (size_t)row * D;
  float* __restrict__ dst = out + (size_t)row * D;

  // base vs ids disambiguation: ids[0] == 0 always; base[0] >= 1 always.
  const int* __restrict__ basep = (candA[0] == 0) ? candB : candA;
  const unsigned len = (unsigned)basep[row];

  // Atomic-pruning threshold (~5 sigma margin; verified exactly below).
  unsigned T = (unsigned)(((unsigned long long)(len + 96u) * NB) / D + 1u);
  if (T > NB) T = NB;

  // ---- zero-fill dead region [len, D) NOW: overlaps phase 1, disjoint
  //      from all live-rank writes ----
#pragma unroll
  for (int k = 0; k < 4; ++k) {
    const unsigned r = (unsigned)(t + k * THREADS);
    if (r < D && r >= len) dst[r] = 0.0f;
  }

  // ---- copy table (NE == THREADS: unconditional); clear histogram ----
  pbase[t] = g_pack[t];
  reinterpret_cast<uint4*>(hist)[t] = make_uint4(0u, 0u, 0u, 0u);
  __syncthreads();

  // ---- phase 1: load, key, bucket; histogram atomic ONLY for bk < T ----
  unsigned kks[4];
  unsigned short bks[4];
  unsigned short ords[4];
#pragma unroll
  for (int k = 0; k < 4; ++k) {
    const int v = t + k * THREADS;
    if (v < D) {
      const unsigned u = __float_as_uint(src[v]);
      const unsigned a = u ^ ((u & 0x80000000u) ? 0xFFFFFFFFu : 0x80000000u);
      const unsigned kk = ~a;                     // ascending kk == desc value
      const unsigned pk = pbase[kk >> 23];
      const unsigned b0 = pk & 0xFFFFu;
      const unsigned n = pk >> 16;
      const unsigned m = (kk >> 7) & 0xFFFFu;
      const unsigned bk = b0 + ((m * n) >> 16);   // exact monotone in kk
      kks[k] = kk;
      bks[k] = (unsigned short)bk;
      ords[k] = (bk < T) ? (unsigned short)atomicAdd(&hist[bk], 1u)
                         : (unsigned short)0;
    }
  }
  __syncthreads();

  // ---- scan (vectorized, packed start|cnt output) + prune verification ----
  for (int attempt = 0; attempt < 2; ++attempt) {
    {
      const uint4 h4 = reinterpret_cast<const uint4*>(hist)[t];
      const unsigned sum = h4.x + h4.y + h4.z + h4.w;
      unsigned v = sum;
#pragma unroll
      for (int d = 1; d < 32; d <<= 1) {
        unsigned nbr = __shfl_up_sync(0xFFFFFFFFu, v, d);
        if ((t & 31) >= d) v += nbr;
      }
      if ((t & 31) == 31) wsum[t >> 5] = v;
      __syncthreads();
      if (t < 16) {
        unsigned w = wsum[t];
#pragma unroll
        for (int d = 1; d < 16; d <<= 1) {
          unsigned nbr = __shfl_up_sync(0xFFFFu, w, d);
          if (t >= d) w += nbr;
        }
        wsum[t] = w;
      }
      __syncthreads();
      const unsigned excl = v - sum + ((t >= 32) ? wsum[(t >> 5) - 1] : 0u);
      reinterpret_cast<uint4*>(startb)[t] = make_uint4(
          excl | (h4.x << 16), (excl + h4.x) | (h4.y << 16),
          (excl + h4.x + h4.y) | (h4.z << 16),
          (excl + h4.x + h4.y + h4.z) | (h4.w << 16));
    }
    __syncthreads();

    if (T >= NB || (startb[T] & 0xFFFFu) >= len) break;  // pruning exact

    // Fallback (prob ~0): count the skipped elements, rescan with T = NB.
#pragma unroll
    for (int k = 0; k < 4; ++k) {
      const int v = t + k * THREADS;
      if (v < D && bks[k] >= T) {
        ords[k] = (unsigned short)atomicAdd(&hist[bks[k]], 1u);
      }
    }
    T = NB;
    __syncthreads();
  }

  // ---- scatter: dead test in registers; singleton -> DIRECT gmem write ----
#pragma unroll
  for (int k = 0; k < 4; ++k) {
    const int v = t + k * THREADS;
    if (v < D) {
      const unsigned bk = bks[k];
      if (bk >= T) {
        bks[k] = 0xFFFFu;                  // pruned: provably rank >= len
      } else {
        const unsigned pc = startb[bk];    // start | cnt<<16
        const unsigned s = pc & 0xFFFFu;
        if (s >= len) {
          bks[k] = 0xFFFFu;                // dead bucket: covered by zero fill
        } else if ((pc >> 16) == 1u) {
          dst[s] = (float)v;               // rank known: final position
          bks[k] = 0xFFFFu;
        } else {
          data[s + ords[k]] = ((unsigned long long)kks[k] << 11) | (unsigned)v;
        }
      }
    }
  }
  __syncthreads();

  // ---- phase 2: rank within live multi buckets -> DIRECT gmem write ----
#pragma unroll
  for (int k = 0; k < 4; ++k) {
    const int v = t + k * THREADS;
    if (v < D && bks[k] != 0xFFFFu) {
      const unsigned pc = startb[bks[k]];
      const unsigned s = pc & 0xFFFFu;
      const unsigned e = s + (pc >> 16);
      const unsigned long long ki =
          ((unsigned long long)kks[k] << 11) | (unsigned)v;
      unsigned r = s;
      for (unsigned j = s; j < e; ++j) r += (data[j] < ki) ? 1u : 0u;
      if (r < len) dst[r] = (float)v;
    }
  }
}

extern "C" void kernel_launch(void* const* d_in, const int* in_sizes, int n_in,
                              void* d_out, int out_size) {
  // to_cut is the (unique) large buffer: P*T*D elements.
  int imax = 0;
  for (int i = 1; i < n_in; ++i)
    if (in_sizes[i] > in_sizes[imax]) imax = i;
  const float* to_cut = (const float*)d_in[imax];

  int others[2], k = 0;
  for (int i = 0; i < n_in && k < 2; ++i)
    if (i != imax) others[k++] = i;
  const int* candA = (const int*)d_in[others[0]];
  const int* candB = (const int*)d_in[others[1]];

  float* out = (float*)d_out;
  const int rows = in_sizes[imax] / D;  // P*T = 8192

  build_base_kernel<<<1, NE>>>();
  cutoutput_bucket_kernel<<<rows, THREADS>>>(to_cut, candA, candB, out);
}